// round 13
// baseline (speedup 1.0000x reference)
#include <cuda_runtime.h>
#include <cuda_bf16.h>
#include <cuda_fp16.h>
#include <math.h>

#define NN 50000
#define EE 800000
#define RR 8
#define NR (NN * RR)
#define NB2 ((NR + 255) / 256)          // 1563
#define W2OFF (9 * 128 * 64)

typedef unsigned long long ull;

// ---------------- scratch ----------------------------------------------------
__device__ __half    g_H[(size_t)NN * 512];     // fp16 projections (51 MB)
__device__ float     g_h1[(size_t)NN * 64];
__device__ float     g_h2[(size_t)NN * 64];
__device__ __half    g_xh[(size_t)NN * 128];
__device__ __half    g_ah[(size_t)NN * 64];
__device__ __half    g_wh[9 * 128 * 64 + 9 * 64 * 64];
__device__ int       g_cnt[NR];
__device__ int       g_ptr[NR + 1];
__device__ int       g_cur[NR];
__device__ int       g_bsum[NB2];
__device__ ull       g_stage[EE];               // (key<<32)|src, key = dst*8+rel
__device__ unsigned  g_packed[EE];              // (rel<<16)|src, grouped by (dst,rel)
__device__ int       g_is64_idx;
__device__ int       g_is64_typ;

// ---------------- dtype helpers ------------------------------------------------
__device__ __forceinline__ int load_src(const void* ei, int e) {
    return g_is64_idx ? (int)((const long long*)ei)[e] : ((const int*)ei)[e];
}
__device__ __forceinline__ int load_dst(const void* ei, int e) {
    return g_is64_idx ? (int)((const long long*)ei)[EE + e] : ((const int*)ei)[EE + e];
}
__device__ __forceinline__ int load_rel(const void* et, int e) {
    return g_is64_typ ? (int)((const long long*)et)[e] : ((const int*)et)[e];
}

// ---------------- fused prep -------------------------------------------------------
#define W1_F2   32768
#define R1_F2   4096
#define W2_F2   16384
#define R2_F2   2048
#define WT_F2   (W1_F2 + R1_F2 + W2_F2 + R2_F2)
#define X_F2    (NN * 128 / 2)
#define PREP_MAX X_F2

__global__ void prep_kernel(const unsigned* __restrict__ idx,
                            const unsigned* __restrict__ typ,
                            const float* __restrict__ x,
                            const float* __restrict__ W1, const float* __restrict__ r1,
                            const float* __restrict__ W2, const float* __restrict__ r2) {
    int i = blockIdx.x * blockDim.x + threadIdx.x;
    if (i == 0) {
        unsigned a = 0, b = 0;
        #pragma unroll
        for (int k = 0; k < 64; k++) { a |= idx[2 * k + 1]; b |= typ[2 * k + 1]; }
        g_is64_idx = (a == 0);
        g_is64_typ = (b == 0);
    }
    if (i < NR) g_cnt[i] = 0;
    if (i < WT_F2) {
        const float2* src;
        int off;
        if (i < W1_F2)                      { src = (const float2*)W1; off = i; }
        else if (i < W1_F2 + R1_F2)         { src = (const float2*)r1; off = i - W1_F2; }
        else if (i < W1_F2 + R1_F2 + W2_F2) { src = (const float2*)W2; off = i - W1_F2 - R1_F2; }
        else                                { src = (const float2*)r2; off = i - W1_F2 - R1_F2 - W2_F2; }
        float2 v = src[off];
        ((__half2*)g_wh)[i] = __floats2half2_rn(v.x, v.y);
    }
    if (i < X_F2) {
        float2 v = ((const float2*)x)[i];
        ((__half2*)g_xh)[i] = __floats2half2_rn(v.x, v.y);
    }
}

// ---------------- hist + stage (1 edge / thread — proven) ------------------------
__global__ void hist_stage_kernel(const void* __restrict__ ei,
                                  const void* __restrict__ et) {
    int e = blockIdx.x * blockDim.x + threadIdx.x;
    if (e >= EE) return;
    int src = load_src(ei, e);
    int dst = load_dst(ei, e);
    int rel = load_rel(et, e);
    if ((unsigned)src >= NN || (unsigned)dst >= NN || (unsigned)rel >= RR) {
        g_stage[e] = ~0ull;
        return;
    }
    int key = dst * RR + rel;
    atomicAdd(&g_cnt[key], 1);
    g_stage[e] = ((ull)(unsigned)key << 32) | (unsigned)src;
}

// ---------------- 2-kernel scan over 400k counts ----------------------------------
__global__ void blocksum_kernel() {
    int b = blockIdx.x, t = threadIdx.x, i = b * 256 + t;
    int v = (i < NR) ? g_cnt[i] : 0;
    __shared__ int sh[8];
    int lane = t & 31, wid = t >> 5;
    #pragma unroll
    for (int o = 16; o > 0; o >>= 1) v += __shfl_xor_sync(0xffffffffu, v, o);
    if (lane == 0) sh[wid] = v;
    __syncthreads();
    if (t == 0) {
        int s = 0;
        #pragma unroll
        for (int j = 0; j < 8; j++) s += sh[j];
        g_bsum[b] = s;
    }
}

__device__ __forceinline__ int block_incl_scan256(int v, int t) {
    __shared__ int ws[8];
    int lane = t & 31, wid = t >> 5;
    int x = v;
    #pragma unroll
    for (int o = 1; o < 32; o <<= 1) {
        int y = __shfl_up_sync(0xffffffffu, x, o);
        if (lane >= o) x += y;
    }
    if (lane == 31) ws[wid] = x;
    __syncthreads();
    if (wid == 0) {
        int s = (lane < 8) ? ws[lane] : 0;
        #pragma unroll
        for (int o = 1; o < 8; o <<= 1) {
            int y = __shfl_up_sync(0xffffffffu, s, o);
            if (lane >= o) s += y;
        }
        if (lane < 8) ws[lane] = s;
    }
    __syncthreads();
    if (wid > 0) x += ws[wid - 1];
    return x;
}

__global__ void offsets2_kernel() {
    int b = blockIdx.x, t = threadIdx.x, i = b * 256 + t;
    int part = 0;
    for (int j = t; j < b; j += 256) part += g_bsum[j];
    __shared__ int red[8];
    __shared__ int sprefix;
    int lane = t & 31, wid = t >> 5;
    #pragma unroll
    for (int o = 16; o > 0; o >>= 1) part += __shfl_xor_sync(0xffffffffu, part, o);
    if (lane == 0) red[wid] = part;
    __syncthreads();
    if (t == 0) {
        int s = 0;
        #pragma unroll
        for (int j = 0; j < 8; j++) s += red[j];
        sprefix = s;
    }
    __syncthreads();

    int v = (i < NR) ? g_cnt[i] : 0;
    int incl = block_incl_scan256(v, t);
    int excl = sprefix + incl - v;
    if (i < NR) { g_ptr[i] = excl; g_cur[i] = excl; }
    if (b == NB2 - 1 && t == 255) g_ptr[NR] = sprefix + incl;
}

// ---------------- scatter (1 edge / thread — proven) ------------------------------
__global__ void scatter_kernel() {
    int e = blockIdx.x * blockDim.x + threadIdx.x;
    if (e >= EE) return;
    ull s = g_stage[e];
    if (s == ~0ull) return;
    int key = (int)(s >> 32);
    unsigned src = (unsigned)s;
    int pos = atomicAdd(&g_cur[key], 1);
    g_packed[pos] = ((unsigned)(key & 7) << 16) | src;
}

// ---------------- tensor-core helpers ------------------------------------------
__device__ __forceinline__ unsigned smem_u32(const void* p) {
    return (unsigned)__cvta_generic_to_shared(p);
}
__device__ __forceinline__ void ldsm4(unsigned& r0, unsigned& r1, unsigned& r2,
                                      unsigned& r3, unsigned addr) {
    asm volatile("ldmatrix.sync.aligned.m8n8.x4.shared.b16 {%0,%1,%2,%3}, [%4];"
                 : "=r"(r0), "=r"(r1), "=r"(r2), "=r"(r3) : "r"(addr));
}
__device__ __forceinline__ void ldsm4t(unsigned& r0, unsigned& r1, unsigned& r2,
                                       unsigned& r3, unsigned addr) {
    asm volatile("ldmatrix.sync.aligned.m8n8.x4.trans.shared.b16 {%0,%1,%2,%3}, [%4];"
                 : "=r"(r0), "=r"(r1), "=r"(r2), "=r"(r3) : "r"(addr));
}
__device__ __forceinline__ void mma16816h(float* d, unsigned a0, unsigned a1,
                                          unsigned a2, unsigned a3,
                                          unsigned b0, unsigned b1) {
    asm volatile(
        "mma.sync.aligned.m16n8k16.row.col.f32.f16.f16.f32 "
        "{%0,%1,%2,%3},{%4,%5,%6,%7},{%8,%9},{%0,%1,%2,%3};"
        : "+f"(d[0]), "+f"(d[1]), "+f"(d[2]), "+f"(d[3])
        : "r"(a0), "r"(a1), "r"(a2), "r"(a3), "r"(b0), "r"(b1));
}

// ---------------- fp16 tensor GEMM: C[128 x 64] per block -----------------------
template <int K>
__global__ void __launch_bounds__(256)
tgemm_kernel(const __half* __restrict__ A, const float* __restrict__ bias,
             int woff, int layer) {
    __shared__ __half sA[128 * 40];
    __shared__ __half sB[32 * 72];

    int tid = threadIdx.x, warp = tid >> 5, lane = tid & 31;
    int m0 = blockIdx.x * 128, rel = blockIdx.y;

    const __half* W = g_wh + woff + (size_t)rel * K * 64;

    float acc[8][4];
    #pragma unroll
    for (int j = 0; j < 8; j++)
        #pragma unroll
        for (int i = 0; i < 4; i++) acc[j][i] = 0.f;

    const uint4 z4 = make_uint4(0, 0, 0, 0);

    for (int kt = 0; kt < K; kt += 32) {
        __syncthreads();
        #pragma unroll
        for (int i = 0; i < 2; i++) {
            int seg = tid + i * 256;
            int row = seg >> 2, s = seg & 3;
            int gr = m0 + row;
            uint4 vh = z4;
            if (gr < NN) vh = *(const uint4*)&A[(size_t)gr * K + kt + s * 8];
            *(uint4*)&sA[row * 40 + s * 8] = vh;
        }
        {
            int row = tid >> 3, s = tid & 7;
            *(uint4*)&sB[row * 72 + s * 8] = *(const uint4*)&W[(size_t)(kt + row) * 64 + s * 8];
        }
        __syncthreads();

        #pragma unroll
        for (int ks = 0; ks < 32; ks += 16) {
            unsigned ah[4];
            unsigned aoff = (warp * 16 + (lane & 15)) * 40 + ks + (lane >> 4) * 8;
            ldsm4(ah[0], ah[1], ah[2], ah[3], smem_u32(&sA[aoff]));
            #pragma unroll
            for (int jj = 0; jj < 4; jj++) {
                int g = lane >> 3;
                int brow = ks + (lane & 7) + (g & 1) * 8;
                int bcol = jj * 16 + (g >> 1) * 8;
                unsigned bh[4];
                ldsm4t(bh[0], bh[1], bh[2], bh[3], smem_u32(&sB[brow * 72 + bcol]));
                mma16816h(acc[2 * jj],     ah[0], ah[1], ah[2], ah[3], bh[0], bh[1]);
                mma16816h(acc[2 * jj + 1], ah[0], ah[1], ah[2], ah[3], bh[2], bh[3]);
            }
        }
    }

    int row = m0 + warp * 16 + (lane >> 2);
    int cb  = (lane & 3) * 2;
    if (rel < 8) {
        #pragma unroll
        for (int j = 0; j < 8; j++) {
            int col = rel * 64 + j * 8 + cb;
            if (row < NN)
                *(__half2*)&g_H[(size_t)row * 512 + col] =
                    __floats2half2_rn(acc[j][0], acc[j][1]);
            if (row + 8 < NN)
                *(__half2*)&g_H[(size_t)(row + 8) * 512 + col] =
                    __floats2half2_rn(acc[j][2], acc[j][3]);
        }
    } else {
        float* C = (layer == 1) ? g_h1 : g_h2;
        #pragma unroll
        for (int j = 0; j < 8; j++) {
            int col = j * 8 + cb;
            float b0 = bias[col], b1 = bias[col + 1];
            if (row < NN)
                *(float2*)&C[(size_t)row * 64 + col] =
                    make_float2(acc[j][0] + b0, acc[j][1] + b1);
            if (row + 8 < NN)
                *(float2*)&C[(size_t)(row + 8) * 64 + col] =
                    make_float2(acc[j][2] + b0, acc[j][3] + b1);
        }
    }
}

// ---------------- aggregation: TWO warps per node, MLP-8 fp16 gather --------------
// Block = 256 threads = 8 warps = 4 nodes. Warp pair (2j, 2j+1) splits the node's
// edge list in half; odd warp deposits partials to smem; even warp combines+writes.
__global__ void __launch_bounds__(256)
agg_kernel(int sel) {
    __shared__ float2 part[4][32];

    int tid  = threadIdx.x;
    int warp = tid >> 5, lane = tid & 31;
    int pair = warp >> 1, p = warp & 1;
    int gw = blockIdx.x * 4 + pair;
    bool valid = (gw < NN);

    float ax = 0.f, ay = 0.f;
    float inv8 = 0.f;

    if (valid) {
        int p0 = 0, p1 = 0;
        if (lane < 8) {
            p0 = g_ptr[gw * RR + lane];
            p1 = g_ptr[gw * RR + lane + 1];
        }
        inv8 = (lane < 8) ? 1.f / (float)max(p1 - p0, 1) : 0.f;
        int beg = __shfl_sync(0xffffffffu, p0, 0);
        int end = __shfl_sync(0xffffffffu, p1, 7);
        int h = (end - beg) >> 1;
        int b = p ? (beg + h) : beg;
        int e2 = p ? end : (beg + h);

        int e = b;
        for (; e + 8 <= e2; e += 8) {
            unsigned q[8];
            #pragma unroll
            for (int u = 0; u < 8; u++) q[u] = g_packed[e + u];
            __half2 v[8];
            #pragma unroll
            for (int u = 0; u < 8; u++)
                v[u] = *(const __half2*)&g_H[(size_t)(q[u] & 0xffff) * 512 +
                                             (q[u] >> 16) * 64 + lane * 2];
            #pragma unroll
            for (int u = 0; u < 8; u++) {
                float iv = __shfl_sync(0xffffffffu, inv8, q[u] >> 16);
                float2 f = __half22float2(v[u]);
                ax = fmaf(f.x, iv, ax);
                ay = fmaf(f.y, iv, ay);
            }
        }
        for (; e < e2; e++) {
            unsigned q = g_packed[e];
            float iv = __shfl_sync(0xffffffffu, inv8, q >> 16);
            __half2 hv = *(const __half2*)&g_H[(size_t)(q & 0xffff) * 512 +
                                               (q >> 16) * 64 + lane * 2];
            float2 f = __half22float2(hv);
            ax = fmaf(f.x, iv, ax);
            ay = fmaf(f.y, iv, ay);
        }
    }

    if (p == 1) part[pair][lane] = make_float2(ax, ay);
    __syncthreads();

    if (p == 0 && valid) {
        float2 o = part[pair][lane];
        ax += o.x;
        ay += o.y;
        const float* base = (sel == 1) ? g_h1 : g_h2;
        float2 b = *(const float2*)&base[(size_t)gw * 64 + lane * 2];
        float o0 = b.x + ax, o1 = b.y + ay;
        o0 = o0 > 0.f ? o0 : 0.f;
        o1 = o1 > 0.f ? o1 : 0.f;
        if (sel == 1) {
            ((__half2*)g_ah)[gw * 32 + lane] = __floats2half2_rn(o0, o1);
        } else {
            *(float2*)&g_h2[(size_t)gw * 64 + lane * 2] = make_float2(o0, o1);
        }
    }
}

// ---------------- final: logits = h2 @ Wl + bl, then log_softmax -----------------
__global__ void __launch_bounds__(256)
final_kernel(const float* __restrict__ Wl, const float* __restrict__ bl,
             float* __restrict__ out) {
    __shared__ float sW[64 * 40];
    __shared__ float sb[40];
    __shared__ float srow[8][64];
    int t = threadIdx.x;
    for (int i = t; i < 64 * 40; i += 256) sW[i] = Wl[i];
    if (t < 40) sb[t] = bl[t];
    __syncthreads();

    int warp = t >> 5, lane = t & 31;
    int n = blockIdx.x * 8 + warp;
    if (n < NN) {
        srow[warp][lane]      = g_h2[(size_t)n * 64 + lane];
        srow[warp][lane + 32] = g_h2[(size_t)n * 64 + 32 + lane];
    }
    __syncwarp();

    float v1 = -1e30f, v2 = -1e30f;
    if (n < NN) {
        float d = sb[lane];
        #pragma unroll
        for (int k = 0; k < 64; k++) d += srow[warp][k] * sW[k * 40 + lane];
        v1 = d;
        if (lane < 8) {
            float d2 = sb[lane + 32];
            #pragma unroll
            for (int k = 0; k < 64; k++) d2 += srow[warp][k] * sW[k * 40 + lane + 32];
            v2 = d2;
        }
    }
    float m = fmaxf(v1, v2);
    #pragma unroll
    for (int o = 16; o > 0; o >>= 1) m = fmaxf(m, __shfl_xor_sync(0xffffffffu, m, o));
    float e1 = __expf(v1 - m);
    float e2 = (lane < 8) ? __expf(v2 - m) : 0.f;
    float s = e1 + e2;
    #pragma unroll
    for (int o = 16; o > 0; o >>= 1) s += __shfl_xor_sync(0xffffffffu, s, o);
    float lse = m + __logf(s);
    if (n < NN) {
        out[(size_t)n * 40 + lane] = v1 - lse;
        if (lane < 8) out[(size_t)n * 40 + 32 + lane] = v2 - lse;
    }
}

// ---------------- launch ---------------------------------------------------------
extern "C" void kernel_launch(void* const* d_in, const int* in_sizes, int n_in,
                              void* d_out, int out_size) {
    const float* x     = (const float*)d_in[0];
    const void*  ei    = d_in[1];
    const void*  et    = d_in[2];
    const float* W1    = (const float*)d_in[3];
    const float* root1 = (const float*)d_in[4];
    const float* b1    = (const float*)d_in[5];
    const float* W2    = (const float*)d_in[6];
    const float* root2 = (const float*)d_in[7];
    const float* b2    = (const float*)d_in[8];
    const float* Wl    = (const float*)d_in[9];
    const float* bl    = (const float*)d_in[10];
    float*       out   = (float*)d_out;

    __half *xh, *ah;
    cudaGetSymbolAddress((void**)&xh, g_xh);
    cudaGetSymbolAddress((void**)&ah, g_ah);

    // prep + CSR build (2-kernel scan)
    prep_kernel<<<(PREP_MAX + 255) / 256, 256>>>((const unsigned*)ei,
                                                 (const unsigned*)et,
                                                 x, W1, root1, W2, root2);
    hist_stage_kernel<<<(EE + 255) / 256, 256>>>(ei, et);
    blocksum_kernel<<<NB2, 256>>>();
    offsets2_kernel<<<NB2, 256>>>();
    scatter_kernel<<<(EE + 255) / 256, 256>>>();

    dim3 g9((NN + 127) / 128, 9);

    // layer 1
    tgemm_kernel<128><<<g9, 256>>>(xh, b1, 0, 1);
    agg_kernel<<<(NN + 3) / 4, 256>>>(1);     // -> g_ah (fp16)

    // layer 2
    tgemm_kernel<64><<<g9, 256>>>(ah, b2, W2OFF, 2);
    agg_kernel<<<(NN + 3) / 4, 256>>>(2);     // -> g_h2 (fp32)

    final_kernel<<<(NN + 7) / 8, 256>>>(Wl, bl, out);
}

// round 14
// speedup vs baseline: 1.0727x; 1.0727x over previous
#include <cuda_runtime.h>
#include <cuda_bf16.h>
#include <cuda_fp16.h>
#include <math.h>

#define NN 50000
#define EE 800000
#define RR 8
#define NR (NN * RR)
#define NB2 ((NR + 255) / 256)          // 1563
#define W2OFF (9 * 128 * 64)

typedef unsigned long long ull;

// ---------------- scratch ----------------------------------------------------
__device__ __half    g_H[(size_t)NN * 512];     // fp16 projections (51 MB)
__device__ float     g_h1[(size_t)NN * 64];
__device__ float     g_h2[(size_t)NN * 64];
__device__ __half    g_xh[(size_t)NN * 128];
__device__ __half    g_ah[(size_t)NN * 64];
__device__ __half    g_wh[9 * 128 * 64 + 9 * 64 * 64];
__device__ int       g_cnt[NR];
__device__ int       g_ptr[NR + 1];
__device__ int       g_cur[NR];
__device__ int       g_bsum[NB2];
__device__ ull       g_stage[EE];               // (key<<32)|src, key = dst*8+rel
__device__ unsigned  g_packed[EE];              // (rel<<16)|src, grouped by (dst,rel)
__device__ int       g_is64_idx;
__device__ int       g_is64_typ;

// ---------------- dtype helpers ------------------------------------------------
__device__ __forceinline__ int load_src(const void* ei, int e) {
    return g_is64_idx ? (int)((const long long*)ei)[e] : ((const int*)ei)[e];
}
__device__ __forceinline__ int load_dst(const void* ei, int e) {
    return g_is64_idx ? (int)((const long long*)ei)[EE + e] : ((const int*)ei)[EE + e];
}
__device__ __forceinline__ int load_rel(const void* et, int e) {
    return g_is64_typ ? (int)((const long long*)et)[e] : ((const int*)et)[e];
}

// ---------------- fused prep -------------------------------------------------------
#define W1_F2   32768
#define R1_F2   4096
#define W2_F2   16384
#define R2_F2   2048
#define WT_F2   (W1_F2 + R1_F2 + W2_F2 + R2_F2)
#define X_F2    (NN * 128 / 2)
#define PREP_MAX X_F2

__global__ void prep_kernel(const unsigned* __restrict__ idx,
                            const unsigned* __restrict__ typ,
                            const float* __restrict__ x,
                            const float* __restrict__ W1, const float* __restrict__ r1,
                            const float* __restrict__ W2, const float* __restrict__ r2) {
    int i = blockIdx.x * blockDim.x + threadIdx.x;
    if (i == 0) {
        unsigned a = 0, b = 0;
        #pragma unroll
        for (int k = 0; k < 64; k++) { a |= idx[2 * k + 1]; b |= typ[2 * k + 1]; }
        g_is64_idx = (a == 0);
        g_is64_typ = (b == 0);
    }
    if (i < NR) g_cnt[i] = 0;
    if (i < WT_F2) {
        const float2* src;
        int off;
        if (i < W1_F2)                      { src = (const float2*)W1; off = i; }
        else if (i < W1_F2 + R1_F2)         { src = (const float2*)r1; off = i - W1_F2; }
        else if (i < W1_F2 + R1_F2 + W2_F2) { src = (const float2*)W2; off = i - W1_F2 - R1_F2; }
        else                                { src = (const float2*)r2; off = i - W1_F2 - R1_F2 - W2_F2; }
        float2 v = src[off];
        ((__half2*)g_wh)[i] = __floats2half2_rn(v.x, v.y);
    }
    if (i < X_F2) {
        float2 v = ((const float2*)x)[i];
        ((__half2*)g_xh)[i] = __floats2half2_rn(v.x, v.y);
    }
}

// ---------------- hist + stage (1 edge / thread — proven) ------------------------
__global__ void hist_stage_kernel(const void* __restrict__ ei,
                                  const void* __restrict__ et) {
    int e = blockIdx.x * blockDim.x + threadIdx.x;
    if (e >= EE) return;
    int src = load_src(ei, e);
    int dst = load_dst(ei, e);
    int rel = load_rel(et, e);
    if ((unsigned)src >= NN || (unsigned)dst >= NN || (unsigned)rel >= RR) {
        g_stage[e] = ~0ull;
        return;
    }
    int key = dst * RR + rel;
    atomicAdd(&g_cnt[key], 1);
    g_stage[e] = ((ull)(unsigned)key << 32) | (unsigned)src;
}

// ---------------- 2-kernel scan over 400k counts ----------------------------------
__global__ void blocksum_kernel() {
    int b = blockIdx.x, t = threadIdx.x, i = b * 256 + t;
    int v = (i < NR) ? g_cnt[i] : 0;
    __shared__ int sh[8];
    int lane = t & 31, wid = t >> 5;
    #pragma unroll
    for (int o = 16; o > 0; o >>= 1) v += __shfl_xor_sync(0xffffffffu, v, o);
    if (lane == 0) sh[wid] = v;
    __syncthreads();
    if (t == 0) {
        int s = 0;
        #pragma unroll
        for (int j = 0; j < 8; j++) s += sh[j];
        g_bsum[b] = s;
    }
}

__device__ __forceinline__ int block_incl_scan256(int v, int t) {
    __shared__ int ws[8];
    int lane = t & 31, wid = t >> 5;
    int x = v;
    #pragma unroll
    for (int o = 1; o < 32; o <<= 1) {
        int y = __shfl_up_sync(0xffffffffu, x, o);
        if (lane >= o) x += y;
    }
    if (lane == 31) ws[wid] = x;
    __syncthreads();
    if (wid == 0) {
        int s = (lane < 8) ? ws[lane] : 0;
        #pragma unroll
        for (int o = 1; o < 8; o <<= 1) {
            int y = __shfl_up_sync(0xffffffffu, s, o);
            if (lane >= o) s += y;
        }
        if (lane < 8) ws[lane] = s;
    }
    __syncthreads();
    if (wid > 0) x += ws[wid - 1];
    return x;
}

__global__ void offsets2_kernel() {
    int b = blockIdx.x, t = threadIdx.x, i = b * 256 + t;
    int part = 0;
    for (int j = t; j < b; j += 256) part += g_bsum[j];
    __shared__ int red[8];
    __shared__ int sprefix;
    int lane = t & 31, wid = t >> 5;
    #pragma unroll
    for (int o = 16; o > 0; o >>= 1) part += __shfl_xor_sync(0xffffffffu, part, o);
    if (lane == 0) red[wid] = part;
    __syncthreads();
    if (t == 0) {
        int s = 0;
        #pragma unroll
        for (int j = 0; j < 8; j++) s += red[j];
        sprefix = s;
    }
    __syncthreads();

    int v = (i < NR) ? g_cnt[i] : 0;
    int incl = block_incl_scan256(v, t);
    int excl = sprefix + incl - v;
    if (i < NR) { g_ptr[i] = excl; g_cur[i] = excl; }
    if (b == NB2 - 1 && t == 255) g_ptr[NR] = sprefix + incl;
}

// ---------------- scatter (1 edge / thread — proven) ------------------------------
__global__ void scatter_kernel() {
    int e = blockIdx.x * blockDim.x + threadIdx.x;
    if (e >= EE) return;
    ull s = g_stage[e];
    if (s == ~0ull) return;
    int key = (int)(s >> 32);
    unsigned src = (unsigned)s;
    int pos = atomicAdd(&g_cur[key], 1);
    g_packed[pos] = ((unsigned)(key & 7) << 16) | src;
}

// ---------------- tensor-core helpers ------------------------------------------
__device__ __forceinline__ unsigned smem_u32(const void* p) {
    return (unsigned)__cvta_generic_to_shared(p);
}
__device__ __forceinline__ void ldsm4(unsigned& r0, unsigned& r1, unsigned& r2,
                                      unsigned& r3, unsigned addr) {
    asm volatile("ldmatrix.sync.aligned.m8n8.x4.shared.b16 {%0,%1,%2,%3}, [%4];"
                 : "=r"(r0), "=r"(r1), "=r"(r2), "=r"(r3) : "r"(addr));
}
__device__ __forceinline__ void ldsm4t(unsigned& r0, unsigned& r1, unsigned& r2,
                                       unsigned& r3, unsigned addr) {
    asm volatile("ldmatrix.sync.aligned.m8n8.x4.trans.shared.b16 {%0,%1,%2,%3}, [%4];"
                 : "=r"(r0), "=r"(r1), "=r"(r2), "=r"(r3) : "r"(addr));
}
__device__ __forceinline__ void mma16816h(float* d, unsigned a0, unsigned a1,
                                          unsigned a2, unsigned a3,
                                          unsigned b0, unsigned b1) {
    asm volatile(
        "mma.sync.aligned.m16n8k16.row.col.f32.f16.f16.f32 "
        "{%0,%1,%2,%3},{%4,%5,%6,%7},{%8,%9},{%0,%1,%2,%3};"
        : "+f"(d[0]), "+f"(d[1]), "+f"(d[2]), "+f"(d[3])
        : "r"(a0), "r"(a1), "r"(a2), "r"(a3), "r"(b0), "r"(b1));
}

// ---------------- fp16 tensor GEMM: C[128 x 64] per block -----------------------
template <int K>
__global__ void __launch_bounds__(256)
tgemm_kernel(const __half* __restrict__ A, const float* __restrict__ bias,
             int woff, int layer) {
    __shared__ __half sA[128 * 40];
    __shared__ __half sB[32 * 72];

    int tid = threadIdx.x, warp = tid >> 5, lane = tid & 31;
    int m0 = blockIdx.x * 128, rel = blockIdx.y;

    const __half* W = g_wh + woff + (size_t)rel * K * 64;

    float acc[8][4];
    #pragma unroll
    for (int j = 0; j < 8; j++)
        #pragma unroll
        for (int i = 0; i < 4; i++) acc[j][i] = 0.f;

    const uint4 z4 = make_uint4(0, 0, 0, 0);

    for (int kt = 0; kt < K; kt += 32) {
        __syncthreads();
        #pragma unroll
        for (int i = 0; i < 2; i++) {
            int seg = tid + i * 256;
            int row = seg >> 2, s = seg & 3;
            int gr = m0 + row;
            uint4 vh = z4;
            if (gr < NN) vh = *(const uint4*)&A[(size_t)gr * K + kt + s * 8];
            *(uint4*)&sA[row * 40 + s * 8] = vh;
        }
        {
            int row = tid >> 3, s = tid & 7;
            *(uint4*)&sB[row * 72 + s * 8] = *(const uint4*)&W[(size_t)(kt + row) * 64 + s * 8];
        }
        __syncthreads();

        #pragma unroll
        for (int ks = 0; ks < 32; ks += 16) {
            unsigned ah[4];
            unsigned aoff = (warp * 16 + (lane & 15)) * 40 + ks + (lane >> 4) * 8;
            ldsm4(ah[0], ah[1], ah[2], ah[3], smem_u32(&sA[aoff]));
            #pragma unroll
            for (int jj = 0; jj < 4; jj++) {
                int g = lane >> 3;
                int brow = ks + (lane & 7) + (g & 1) * 8;
                int bcol = jj * 16 + (g >> 1) * 8;
                unsigned bh[4];
                ldsm4t(bh[0], bh[1], bh[2], bh[3], smem_u32(&sB[brow * 72 + bcol]));
                mma16816h(acc[2 * jj],     ah[0], ah[1], ah[2], ah[3], bh[0], bh[1]);
                mma16816h(acc[2 * jj + 1], ah[0], ah[1], ah[2], ah[3], bh[2], bh[3]);
            }
        }
    }

    int row = m0 + warp * 16 + (lane >> 2);
    int cb  = (lane & 3) * 2;
    if (rel < 8) {
        #pragma unroll
        for (int j = 0; j < 8; j++) {
            int col = rel * 64 + j * 8 + cb;
            if (row < NN)
                *(__half2*)&g_H[(size_t)row * 512 + col] =
                    __floats2half2_rn(acc[j][0], acc[j][1]);
            if (row + 8 < NN)
                *(__half2*)&g_H[(size_t)(row + 8) * 512 + col] =
                    __floats2half2_rn(acc[j][2], acc[j][3]);
        }
    } else {
        float* C = (layer == 1) ? g_h1 : g_h2;
        #pragma unroll
        for (int j = 0; j < 8; j++) {
            int col = j * 8 + cb;
            float b0 = bias[col], b1 = bias[col + 1];
            if (row < NN)
                *(float2*)&C[(size_t)row * 64 + col] =
                    make_float2(acc[j][0] + b0, acc[j][1] + b1);
            if (row + 8 < NN)
                *(float2*)&C[(size_t)(row + 8) * 64 + col] =
                    make_float2(acc[j][2] + b0, acc[j][3] + b1);
        }
    }
}

// ---------------- aggregation: warp per node, software-pipelined MLP-8 gather -----
__global__ void agg_kernel(int sel) {
    int gw   = (blockIdx.x * blockDim.x + threadIdx.x) >> 5;
    int lane = threadIdx.x & 31;
    if (gw >= NN) return;

    int p0 = 0, p1 = 0;
    if (lane < 8) {
        p0 = g_ptr[gw * RR + lane];
        p1 = g_ptr[gw * RR + lane + 1];
    }
    float inv8 = (lane < 8) ? 1.f / (float)max(p1 - p0, 1) : 0.f;
    int beg = __shfl_sync(0xffffffffu, p0, 0);
    int end = __shfl_sync(0xffffffffu, p1, 7);

    float ax = 0.f, ay = 0.f;
    int e = beg;

    unsigned q[8];
    bool have = (e + 8 <= end);
    if (have) {
        #pragma unroll
        for (int u = 0; u < 8; u++) q[u] = g_packed[e + u];
    }
    while (have) {
        // issue gathers for current batch
        __half2 v[8];
        #pragma unroll
        for (int u = 0; u < 8; u++)
            v[u] = *(const __half2*)&g_H[(size_t)(q[u] & 0xffff) * 512 +
                                         (q[u] >> 16) * 64 + lane * 2];
        // prefetch next batch's packed words while gathers are in flight
        int en = e + 8;
        bool haven = (en + 8 <= end);
        unsigned qn[8];
        if (haven) {
            #pragma unroll
            for (int u = 0; u < 8; u++) qn[u] = g_packed[en + u];
        }
        // consume current batch
        #pragma unroll
        for (int u = 0; u < 8; u++) {
            float iv = __shfl_sync(0xffffffffu, inv8, q[u] >> 16);
            float2 f = __half22float2(v[u]);
            ax = fmaf(f.x, iv, ax);
            ay = fmaf(f.y, iv, ay);
        }
        #pragma unroll
        for (int u = 0; u < 8; u++) q[u] = qn[u];
        e = en;
        have = haven;
    }
    for (; e < end; e++) {
        unsigned qq = g_packed[e];
        float iv = __shfl_sync(0xffffffffu, inv8, qq >> 16);
        __half2 hv = *(const __half2*)&g_H[(size_t)(qq & 0xffff) * 512 +
                                           (qq >> 16) * 64 + lane * 2];
        float2 f = __half22float2(hv);
        ax = fmaf(f.x, iv, ax);
        ay = fmaf(f.y, iv, ay);
    }

    const float* base = (sel == 1) ? g_h1 : g_h2;
    float2 b = *(const float2*)&base[(size_t)gw * 64 + lane * 2];
    float o0 = b.x + ax, o1 = b.y + ay;
    o0 = o0 > 0.f ? o0 : 0.f;
    o1 = o1 > 0.f ? o1 : 0.f;
    if (sel == 1) {
        ((__half2*)g_ah)[gw * 32 + lane] = __floats2half2_rn(o0, o1);
    } else {
        *(float2*)&g_h2[(size_t)gw * 64 + lane * 2] = make_float2(o0, o1);
    }
}

// ---------------- final: logits = h2 @ Wl + bl, then log_softmax -----------------
__global__ void __launch_bounds__(256)
final_kernel(const float* __restrict__ Wl, const float* __restrict__ bl,
             float* __restrict__ out) {
    __shared__ float sW[64 * 40];
    __shared__ float sb[40];
    __shared__ float srow[8][64];
    int t = threadIdx.x;
    for (int i = t; i < 64 * 40; i += 256) sW[i] = Wl[i];
    if (t < 40) sb[t] = bl[t];
    __syncthreads();

    int warp = t >> 5, lane = t & 31;
    int n = blockIdx.x * 8 + warp;
    if (n < NN) {
        srow[warp][lane]      = g_h2[(size_t)n * 64 + lane];
        srow[warp][lane + 32] = g_h2[(size_t)n * 64 + 32 + lane];
    }
    __syncwarp();

    float v1 = -1e30f, v2 = -1e30f;
    if (n < NN) {
        float d = sb[lane];
        #pragma unroll
        for (int k = 0; k < 64; k++) d += srow[warp][k] * sW[k * 40 + lane];
        v1 = d;
        if (lane < 8) {
            float d2 = sb[lane + 32];
            #pragma unroll
            for (int k = 0; k < 64; k++) d2 += srow[warp][k] * sW[k * 40 + lane + 32];
            v2 = d2;
        }
    }
    float m = fmaxf(v1, v2);
    #pragma unroll
    for (int o = 16; o > 0; o >>= 1) m = fmaxf(m, __shfl_xor_sync(0xffffffffu, m, o));
    float e1 = __expf(v1 - m);
    float e2 = (lane < 8) ? __expf(v2 - m) : 0.f;
    float s = e1 + e2;
    #pragma unroll
    for (int o = 16; o > 0; o >>= 1) s += __shfl_xor_sync(0xffffffffu, s, o);
    float lse = m + __logf(s);
    if (n < NN) {
        out[(size_t)n * 40 + lane] = v1 - lse;
        if (lane < 8) out[(size_t)n * 40 + 32 + lane] = v2 - lse;
    }
}

// ---------------- launch ---------------------------------------------------------
extern "C" void kernel_launch(void* const* d_in, const int* in_sizes, int n_in,
                              void* d_out, int out_size) {
    const float* x     = (const float*)d_in[0];
    const void*  ei    = d_in[1];
    const void*  et    = d_in[2];
    const float* W1    = (const float*)d_in[3];
    const float* root1 = (const float*)d_in[4];
    const float* b1    = (const float*)d_in[5];
    const float* W2    = (const float*)d_in[6];
    const float* root2 = (const float*)d_in[7];
    const float* b2    = (const float*)d_in[8];
    const float* Wl    = (const float*)d_in[9];
    const float* bl    = (const float*)d_in[10];
    float*       out   = (float*)d_out;

    __half *xh, *ah;
    cudaGetSymbolAddress((void**)&xh, g_xh);
    cudaGetSymbolAddress((void**)&ah, g_ah);

    // prep + CSR build (2-kernel scan)
    prep_kernel<<<(PREP_MAX + 255) / 256, 256>>>((const unsigned*)ei,
                                                 (const unsigned*)et,
                                                 x, W1, root1, W2, root2);
    hist_stage_kernel<<<(EE + 255) / 256, 256>>>(ei, et);
    blocksum_kernel<<<NB2, 256>>>();
    offsets2_kernel<<<NB2, 256>>>();
    scatter_kernel<<<(EE + 255) / 256, 256>>>();

    dim3 g9((NN + 127) / 128, 9);

    // layer 1
    tgemm_kernel<128><<<g9, 256>>>(xh, b1, 0, 1);
    agg_kernel<<<(NN * 32 + 255) / 256, 256>>>(1);     // -> g_ah (fp16)

    // layer 2
    tgemm_kernel<64><<<g9, 256>>>(ah, b2, W2OFF, 2);
    agg_kernel<<<(NN * 32 + 255) / 256, 256>>>(2);     // -> g_h2 (fp32)

    final_kernel<<<(NN + 7) / 8, 256>>>(Wl, bl, out);
}

// round 15
// speedup vs baseline: 1.1036x; 1.0288x over previous
#include <cuda_runtime.h>
#include <cuda_bf16.h>
#include <cuda_fp16.h>
#include <math.h>

#define NN 50000
#define EE 800000
#define RR 8
#define NR (NN * RR)
#define NB2 ((NR + 255) / 256)          // 1563
#define W2OFF (9 * 128 * 64)

typedef unsigned long long ull;

// ---------------- scratch ----------------------------------------------------
__device__ __half    g_H[(size_t)NN * 512];     // fp16 projections (51 MB)
__device__ float     g_h1[(size_t)NN * 64];
__device__ float     g_h2[(size_t)NN * 64];
__device__ __half    g_xh[(size_t)NN * 128];
__device__ __half    g_ah[(size_t)NN * 64];
__device__ __half    g_wh[9 * 128 * 64 + 9 * 64 * 64];
__device__ int       g_cnt[NR];
__device__ int       g_ptr[NR + 1];
__device__ int       g_cur[NR];
__device__ int       g_bsum[NB2];
__device__ ull       g_stage[EE];               // (key<<32)|src, key = dst*8+rel
__device__ unsigned  g_packed[EE];              // (rel<<16)|src, grouped by (dst,rel)
__device__ int       g_is64_idx;
__device__ int       g_is64_typ;

// ---------------- dtype helpers ------------------------------------------------
__device__ __forceinline__ int load_src(const void* ei, int e) {
    return g_is64_idx ? (int)((const long long*)ei)[e] : ((const int*)ei)[e];
}
__device__ __forceinline__ int load_dst(const void* ei, int e) {
    return g_is64_idx ? (int)((const long long*)ei)[EE + e] : ((const int*)ei)[EE + e];
}
__device__ __forceinline__ int load_rel(const void* et, int e) {
    return g_is64_typ ? (int)((const long long*)et)[e] : ((const int*)et)[e];
}

// ---------------- fused prep -------------------------------------------------------
#define W1_F2   32768
#define R1_F2   4096
#define W2_F2   16384
#define R2_F2   2048
#define WT_F2   (W1_F2 + R1_F2 + W2_F2 + R2_F2)
#define X_F2    (NN * 128 / 2)
#define PREP_MAX X_F2

__global__ void prep_kernel(const unsigned* __restrict__ idx,
                            const unsigned* __restrict__ typ,
                            const float* __restrict__ x,
                            const float* __restrict__ W1, const float* __restrict__ r1,
                            const float* __restrict__ W2, const float* __restrict__ r2) {
    int i = blockIdx.x * blockDim.x + threadIdx.x;
    if (i == 0) {
        unsigned a = 0, b = 0;
        #pragma unroll
        for (int k = 0; k < 64; k++) { a |= idx[2 * k + 1]; b |= typ[2 * k + 1]; }
        g_is64_idx = (a == 0);
        g_is64_typ = (b == 0);
    }
    if (i < NR) g_cnt[i] = 0;
    if (i < WT_F2) {
        const float2* src;
        int off;
        if (i < W1_F2)                      { src = (const float2*)W1; off = i; }
        else if (i < W1_F2 + R1_F2)         { src = (const float2*)r1; off = i - W1_F2; }
        else if (i < W1_F2 + R1_F2 + W2_F2) { src = (const float2*)W2; off = i - W1_F2 - R1_F2; }
        else                                { src = (const float2*)r2; off = i - W1_F2 - R1_F2 - W2_F2; }
        float2 v = src[off];
        ((__half2*)g_wh)[i] = __floats2half2_rn(v.x, v.y);
    }
    if (i < X_F2) {
        float2 v = ((const float2*)x)[i];
        ((__half2*)g_xh)[i] = __floats2half2_rn(v.x, v.y);
    }
}

// ---------------- hist + stage (1 edge / thread — proven) ------------------------
__global__ void hist_stage_kernel(const void* __restrict__ ei,
                                  const void* __restrict__ et) {
    int e = blockIdx.x * blockDim.x + threadIdx.x;
    if (e >= EE) return;
    int src = load_src(ei, e);
    int dst = load_dst(ei, e);
    int rel = load_rel(et, e);
    if ((unsigned)src >= NN || (unsigned)dst >= NN || (unsigned)rel >= RR) {
        g_stage[e] = ~0ull;
        return;
    }
    int key = dst * RR + rel;
    atomicAdd(&g_cnt[key], 1);
    g_stage[e] = ((ull)(unsigned)key << 32) | (unsigned)src;
}

// ---------------- 2-kernel scan over 400k counts ----------------------------------
__global__ void blocksum_kernel() {
    int b = blockIdx.x, t = threadIdx.x, i = b * 256 + t;
    int v = (i < NR) ? g_cnt[i] : 0;
    __shared__ int sh[8];
    int lane = t & 31, wid = t >> 5;
    #pragma unroll
    for (int o = 16; o > 0; o >>= 1) v += __shfl_xor_sync(0xffffffffu, v, o);
    if (lane == 0) sh[wid] = v;
    __syncthreads();
    if (t == 0) {
        int s = 0;
        #pragma unroll
        for (int j = 0; j < 8; j++) s += sh[j];
        g_bsum[b] = s;
    }
}

__device__ __forceinline__ int block_incl_scan256(int v, int t) {
    __shared__ int ws[8];
    int lane = t & 31, wid = t >> 5;
    int x = v;
    #pragma unroll
    for (int o = 1; o < 32; o <<= 1) {
        int y = __shfl_up_sync(0xffffffffu, x, o);
        if (lane >= o) x += y;
    }
    if (lane == 31) ws[wid] = x;
    __syncthreads();
    if (wid == 0) {
        int s = (lane < 8) ? ws[lane] : 0;
        #pragma unroll
        for (int o = 1; o < 8; o <<= 1) {
            int y = __shfl_up_sync(0xffffffffu, s, o);
            if (lane >= o) s += y;
        }
        if (lane < 8) ws[lane] = s;
    }
    __syncthreads();
    if (wid > 0) x += ws[wid - 1];
    return x;
}

__global__ void offsets2_kernel() {
    int b = blockIdx.x, t = threadIdx.x, i = b * 256 + t;
    int part = 0;
    for (int j = t; j < b; j += 256) part += g_bsum[j];
    __shared__ int red[8];
    __shared__ int sprefix;
    int lane = t & 31, wid = t >> 5;
    #pragma unroll
    for (int o = 16; o > 0; o >>= 1) part += __shfl_xor_sync(0xffffffffu, part, o);
    if (lane == 0) red[wid] = part;
    __syncthreads();
    if (t == 0) {
        int s = 0;
        #pragma unroll
        for (int j = 0; j < 8; j++) s += red[j];
        sprefix = s;
    }
    __syncthreads();

    int v = (i < NR) ? g_cnt[i] : 0;
    int incl = block_incl_scan256(v, t);
    int excl = sprefix + incl - v;
    if (i < NR) { g_ptr[i] = excl; g_cur[i] = excl; }
    if (b == NB2 - 1 && t == 255) g_ptr[NR] = sprefix + incl;
}

// ---------------- scatter (1 edge / thread — proven) ------------------------------
__global__ void scatter_kernel() {
    int e = blockIdx.x * blockDim.x + threadIdx.x;
    if (e >= EE) return;
    ull s = g_stage[e];
    if (s == ~0ull) return;
    int key = (int)(s >> 32);
    unsigned src = (unsigned)s;
    int pos = atomicAdd(&g_cur[key], 1);
    g_packed[pos] = ((unsigned)(key & 7) << 16) | src;
}

// ---------------- tensor-core helpers ------------------------------------------
__device__ __forceinline__ unsigned smem_u32(const void* p) {
    return (unsigned)__cvta_generic_to_shared(p);
}
__device__ __forceinline__ void ldsm4(unsigned& r0, unsigned& r1, unsigned& r2,
                                      unsigned& r3, unsigned addr) {
    asm volatile("ldmatrix.sync.aligned.m8n8.x4.shared.b16 {%0,%1,%2,%3}, [%4];"
                 : "=r"(r0), "=r"(r1), "=r"(r2), "=r"(r3) : "r"(addr));
}
__device__ __forceinline__ void ldsm4t(unsigned& r0, unsigned& r1, unsigned& r2,
                                       unsigned& r3, unsigned addr) {
    asm volatile("ldmatrix.sync.aligned.m8n8.x4.trans.shared.b16 {%0,%1,%2,%3}, [%4];"
                 : "=r"(r0), "=r"(r1), "=r"(r2), "=r"(r3) : "r"(addr));
}
__device__ __forceinline__ void mma16816h(float* d, unsigned a0, unsigned a1,
                                          unsigned a2, unsigned a3,
                                          unsigned b0, unsigned b1) {
    asm volatile(
        "mma.sync.aligned.m16n8k16.row.col.f32.f16.f16.f32 "
        "{%0,%1,%2,%3},{%4,%5,%6,%7},{%8,%9},{%0,%1,%2,%3};"
        : "+f"(d[0]), "+f"(d[1]), "+f"(d[2]), "+f"(d[3])
        : "r"(a0), "r"(a1), "r"(a2), "r"(a3), "r"(b0), "r"(b1));
}

// ---------------- fp16 tensor GEMM: C[128 x 64] per block, double-buffered --------
template <int K>
__global__ void __launch_bounds__(256)
tgemm_kernel(const __half* __restrict__ A, const float* __restrict__ bias,
             int woff, int layer) {
    __shared__ __half sA[2][128 * 40];
    __shared__ __half sB[2][32 * 72];

    int tid = threadIdx.x, warp = tid >> 5, lane = tid & 31;
    int m0 = blockIdx.x * 128, rel = blockIdx.y;

    const __half* W = g_wh + woff + (size_t)rel * K * 64;

    float acc[8][4];
    #pragma unroll
    for (int j = 0; j < 8; j++)
        #pragma unroll
        for (int i = 0; i < 4; i++) acc[j][i] = 0.f;

    const uint4 z4 = make_uint4(0, 0, 0, 0);

    // per-thread load coordinates (constant across chunks)
    int ar0 = (tid + 0)   >> 2, as0 = (tid + 0)   & 3;   // A row/seg, part 1
    int ar1 = (tid + 256) >> 2, as1 = (tid + 256) & 3;   // A row/seg, part 2
    int brow = tid >> 3,  bs = tid & 7;                  // B row/seg

    // preload chunk 0
    {
        uint4 v0 = z4, v1 = z4;
        if (m0 + ar0 < NN) v0 = *(const uint4*)&A[(size_t)(m0 + ar0) * K + as0 * 8];
        if (m0 + ar1 < NN) v1 = *(const uint4*)&A[(size_t)(m0 + ar1) * K + as1 * 8];
        *(uint4*)&sA[0][ar0 * 40 + as0 * 8] = v0;
        *(uint4*)&sA[0][ar1 * 40 + as1 * 8] = v1;
        *(uint4*)&sB[0][brow * 72 + bs * 8] = *(const uint4*)&W[(size_t)brow * 64 + bs * 8];
    }
    __syncthreads();

    #pragma unroll
    for (int it = 0; it < K / 32; it++) {
        int p = it & 1;
        int ktn = (it + 1) * 32;

        // 1) issue next chunk's global loads into registers
        uint4 nA0 = z4, nA1 = z4, nB = z4;
        if (ktn < K) {
            if (m0 + ar0 < NN) nA0 = *(const uint4*)&A[(size_t)(m0 + ar0) * K + ktn + as0 * 8];
            if (m0 + ar1 < NN) nA1 = *(const uint4*)&A[(size_t)(m0 + ar1) * K + ktn + as1 * 8];
            nB = *(const uint4*)&W[(size_t)(ktn + brow) * 64 + bs * 8];
        }

        // 2) compute current chunk while loads are in flight
        #pragma unroll
        for (int ks = 0; ks < 32; ks += 16) {
            unsigned ah[4];
            unsigned aoff = (warp * 16 + (lane & 15)) * 40 + ks + (lane >> 4) * 8;
            ldsm4(ah[0], ah[1], ah[2], ah[3], smem_u32(&sA[p][aoff]));
            #pragma unroll
            for (int jj = 0; jj < 4; jj++) {
                int g = lane >> 3;
                int br = ks + (lane & 7) + (g & 1) * 8;
                int bc = jj * 16 + (g >> 1) * 8;
                unsigned bh[4];
                ldsm4t(bh[0], bh[1], bh[2], bh[3], smem_u32(&sB[p][br * 72 + bc]));
                mma16816h(acc[2 * jj],     ah[0], ah[1], ah[2], ah[3], bh[0], bh[1]);
                mma16816h(acc[2 * jj + 1], ah[0], ah[1], ah[2], ah[3], bh[2], bh[3]);
            }
        }

        // 3) stage next chunk, 4) single barrier
        if (ktn < K) {
            *(uint4*)&sA[1 - p][ar0 * 40 + as0 * 8] = nA0;
            *(uint4*)&sA[1 - p][ar1 * 40 + as1 * 8] = nA1;
            *(uint4*)&sB[1 - p][brow * 72 + bs * 8] = nB;
            __syncthreads();
        }
    }

    int row = m0 + warp * 16 + (lane >> 2);
    int cb  = (lane & 3) * 2;
    if (rel < 8) {
        #pragma unroll
        for (int j = 0; j < 8; j++) {
            int col = rel * 64 + j * 8 + cb;
            if (row < NN)
                *(__half2*)&g_H[(size_t)row * 512 + col] =
                    __floats2half2_rn(acc[j][0], acc[j][1]);
            if (row + 8 < NN)
                *(__half2*)&g_H[(size_t)(row + 8) * 512 + col] =
                    __floats2half2_rn(acc[j][2], acc[j][3]);
        }
    } else {
        float* C = (layer == 1) ? g_h1 : g_h2;
        #pragma unroll
        for (int j = 0; j < 8; j++) {
            int col = j * 8 + cb;
            float b0 = bias[col], b1 = bias[col + 1];
            if (row < NN)
                *(float2*)&C[(size_t)row * 64 + col] =
                    make_float2(acc[j][0] + b0, acc[j][1] + b1);
            if (row + 8 < NN)
                *(float2*)&C[(size_t)(row + 8) * 64 + col] =
                    make_float2(acc[j][2] + b0, acc[j][3] + b1);
        }
    }
}

// ---------------- aggregation: warp per node, MLP-8 fp16 gather (R12 exact) ------
__global__ void agg_kernel(int sel) {
    int gw   = (blockIdx.x * blockDim.x + threadIdx.x) >> 5;
    int lane = threadIdx.x & 31;
    if (gw >= NN) return;

    int p0 = 0, p1 = 0;
    if (lane < 8) {
        p0 = g_ptr[gw * RR + lane];
        p1 = g_ptr[gw * RR + lane + 1];
    }
    float inv8 = (lane < 8) ? 1.f / (float)max(p1 - p0, 1) : 0.f;
    int beg = __shfl_sync(0xffffffffu, p0, 0);
    int end = __shfl_sync(0xffffffffu, p1, 7);

    float ax = 0.f, ay = 0.f;
    int e = beg;
    for (; e + 8 <= end; e += 8) {
        unsigned q[8];
        #pragma unroll
        for (int u = 0; u < 8; u++) q[u] = g_packed[e + u];
        __half2 v[8];
        #pragma unroll
        for (int u = 0; u < 8; u++)
            v[u] = *(const __half2*)&g_H[(size_t)(q[u] & 0xffff) * 512 +
                                         (q[u] >> 16) * 64 + lane * 2];
        #pragma unroll
        for (int u = 0; u < 8; u++) {
            float iv = __shfl_sync(0xffffffffu, inv8, q[u] >> 16);
            float2 f = __half22float2(v[u]);
            ax = fmaf(f.x, iv, ax);
            ay = fmaf(f.y, iv, ay);
        }
    }
    for (; e < end; e++) {
        unsigned q = g_packed[e];
        float iv = __shfl_sync(0xffffffffu, inv8, q >> 16);
        __half2 hv = *(const __half2*)&g_H[(size_t)(q & 0xffff) * 512 +
                                           (q >> 16) * 64 + lane * 2];
        float2 f = __half22float2(hv);
        ax = fmaf(f.x, iv, ax);
        ay = fmaf(f.y, iv, ay);
    }

    const float* base = (sel == 1) ? g_h1 : g_h2;
    float2 b = *(const float2*)&base[(size_t)gw * 64 + lane * 2];
    float o0 = b.x + ax, o1 = b.y + ay;
    o0 = o0 > 0.f ? o0 : 0.f;
    o1 = o1 > 0.f ? o1 : 0.f;
    if (sel == 1) {
        ((__half2*)g_ah)[gw * 32 + lane] = __floats2half2_rn(o0, o1);
    } else {
        *(float2*)&g_h2[(size_t)gw * 64 + lane * 2] = make_float2(o0, o1);
    }
}

// ---------------- final: logits = h2 @ Wl + bl, then log_softmax -----------------
__global__ void __launch_bounds__(256)
final_kernel(const float* __restrict__ Wl, const float* __restrict__ bl,
             float* __restrict__ out) {
    __shared__ float sW[64 * 40];
    __shared__ float sb[40];
    __shared__ float srow[8][64];
    int t = threadIdx.x;
    for (int i = t; i < 64 * 40; i += 256) sW[i] = Wl[i];
    if (t < 40) sb[t] = bl[t];
    __syncthreads();

    int warp = t >> 5, lane = t & 31;
    int n = blockIdx.x * 8 + warp;
    if (n < NN) {
        srow[warp][lane]      = g_h2[(size_t)n * 64 + lane];
        srow[warp][lane + 32] = g_h2[(size_t)n * 64 + 32 + lane];
    }
    __syncwarp();

    float v1 = -1e30f, v2 = -1e30f;
    if (n < NN) {
        float d = sb[lane];
        #pragma unroll
        for (int k = 0; k < 64; k++) d += srow[warp][k] * sW[k * 40 + lane];
        v1 = d;
        if (lane < 8) {
            float d2 = sb[lane + 32];
            #pragma unroll
            for (int k = 0; k < 64; k++) d2 += srow[warp][k] * sW[k * 40 + lane + 32];
            v2 = d2;
        }
    }
    float m = fmaxf(v1, v2);
    #pragma unroll
    for (int o = 16; o > 0; o >>= 1) m = fmaxf(m, __shfl_xor_sync(0xffffffffu, m, o));
    float e1 = __expf(v1 - m);
    float e2 = (lane < 8) ? __expf(v2 - m) : 0.f;
    float s = e1 + e2;
    #pragma unroll
    for (int o = 16; o > 0; o >>= 1) s += __shfl_xor_sync(0xffffffffu, s, o);
    float lse = m + __logf(s);
    if (n < NN) {
        out[(size_t)n * 40 + lane] = v1 - lse;
        if (lane < 8) out[(size_t)n * 40 + 32 + lane] = v2 - lse;
    }
}

// ---------------- launch ---------------------------------------------------------
extern "C" void kernel_launch(void* const* d_in, const int* in_sizes, int n_in,
                              void* d_out, int out_size) {
    const float* x     = (const float*)d_in[0];
    const void*  ei    = d_in[1];
    const void*  et    = d_in[2];
    const float* W1    = (const float*)d_in[3];
    const float* root1 = (const float*)d_in[4];
    const float* b1    = (const float*)d_in[5];
    const float* W2    = (const float*)d_in[6];
    const float* root2 = (const float*)d_in[7];
    const float* b2    = (const float*)d_in[8];
    const float* Wl    = (const float*)d_in[9];
    const float* bl    = (const float*)d_in[10];
    float*       out   = (float*)d_out;

    __half *xh, *ah;
    cudaGetSymbolAddress((void**)&xh, g_xh);
    cudaGetSymbolAddress((void**)&ah, g_ah);

    // prep + CSR build (2-kernel scan)
    prep_kernel<<<(PREP_MAX + 255) / 256, 256>>>((const unsigned*)ei,
                                                 (const unsigned*)et,
                                                 x, W1, root1, W2, root2);
    hist_stage_kernel<<<(EE + 255) / 256, 256>>>(ei, et);
    blocksum_kernel<<<NB2, 256>>>();
    offsets2_kernel<<<NB2, 256>>>();
    scatter_kernel<<<(EE + 255) / 256, 256>>>();

    dim3 g9((NN + 127) / 128, 9);

    // layer 1
    tgemm_kernel<128><<<g9, 256>>>(xh, b1, 0, 1);
    agg_kernel<<<(NN * 32 + 255) / 256, 256>>>(1);     // -> g_ah (fp16)

    // layer 2
    tgemm_kernel<64><<<g9, 256>>>(ah, b2, W2OFF, 2);
    agg_kernel<<<(NN * 32 + 255) / 256, 256>>>(2);     // -> g_h2 (fp32)

    final_kernel<<<(NN + 7) / 8, 256>>>(Wl, bl, out);
}

// round 16
// speedup vs baseline: 1.1061x; 1.0023x over previous
#include <cuda_runtime.h>
#include <cuda_bf16.h>
#include <cuda_fp16.h>
#include <math.h>

#define NN 50000
#define EE 800000
#define RR 8
#define NR (NN * RR)
#define NB2 ((NR + 255) / 256)          // 1563
#define W2OFF (9 * 128 * 64)

typedef unsigned long long ull;

// ---------------- scratch ----------------------------------------------------
__device__ __half    g_H[(size_t)NN * 512];     // fp16 projections (51 MB)
__device__ float     g_h1[(size_t)NN * 64];
__device__ float     g_h2[(size_t)NN * 64];
__device__ __half    g_xh[(size_t)NN * 128];
__device__ __half    g_ah[(size_t)NN * 64];
__device__ __half    g_wh[9 * 128 * 64 + 9 * 64 * 64];
__device__ int       g_cnt[NR];
__device__ int       g_ptr[NR + 1];
__device__ int       g_cur[NR];
__device__ int       g_bsum[NB2];
__device__ ull       g_stage[EE];               // (key<<32)|src, key = dst*8+rel
__device__ unsigned  g_packed[EE];              // (rel<<16)|src, grouped by (dst,rel)
__device__ int       g_is64_idx;
__device__ int       g_is64_typ;

// ---------------- dtype helpers ------------------------------------------------
__device__ __forceinline__ int load_src(const void* ei, int e) {
    return g_is64_idx ? (int)((const long long*)ei)[e] : ((const int*)ei)[e];
}
__device__ __forceinline__ int load_dst(const void* ei, int e) {
    return g_is64_idx ? (int)((const long long*)ei)[EE + e] : ((const int*)ei)[EE + e];
}
__device__ __forceinline__ int load_rel(const void* et, int e) {
    return g_is64_typ ? (int)((const long long*)et)[e] : ((const int*)et)[e];
}

// ---------------- prep (edge side): zero counts + dtype detect --------------------
__global__ void prep_edge_kernel(const unsigned* __restrict__ idx,
                                 const unsigned* __restrict__ typ) {
    int i = blockIdx.x * blockDim.x + threadIdx.x;
    if (i == 0) {
        unsigned a = 0, b = 0;
        #pragma unroll
        for (int k = 0; k < 64; k++) { a |= idx[2 * k + 1]; b |= typ[2 * k + 1]; }
        g_is64_idx = (a == 0);
        g_is64_typ = (b == 0);
    }
    if (i < NR) g_cnt[i] = 0;
}

// ---------------- prep (dense side): fp16 conversions -----------------------------
#define W1_F2   32768
#define R1_F2   4096
#define W2_F2   16384
#define R2_F2   2048
#define WT_F2   (W1_F2 + R1_F2 + W2_F2 + R2_F2)
#define X_F2    (NN * 128 / 2)

__global__ void prep_dense_kernel(const float* __restrict__ x,
                                  const float* __restrict__ W1, const float* __restrict__ r1,
                                  const float* __restrict__ W2, const float* __restrict__ r2) {
    int i = blockIdx.x * blockDim.x + threadIdx.x;
    if (i < WT_F2) {
        const float2* src;
        int off;
        if (i < W1_F2)                      { src = (const float2*)W1; off = i; }
        else if (i < W1_F2 + R1_F2)         { src = (const float2*)r1; off = i - W1_F2; }
        else if (i < W1_F2 + R1_F2 + W2_F2) { src = (const float2*)W2; off = i - W1_F2 - R1_F2; }
        else                                { src = (const float2*)r2; off = i - W1_F2 - R1_F2 - W2_F2; }
        float2 v = src[off];
        ((__half2*)g_wh)[i] = __floats2half2_rn(v.x, v.y);
    }
    if (i < X_F2) {
        float2 v = ((const float2*)x)[i];
        ((__half2*)g_xh)[i] = __floats2half2_rn(v.x, v.y);
    }
}

// ---------------- hist + stage (1 edge / thread — proven) ------------------------
__global__ void hist_stage_kernel(const void* __restrict__ ei,
                                  const void* __restrict__ et) {
    int e = blockIdx.x * blockDim.x + threadIdx.x;
    if (e >= EE) return;
    int src = load_src(ei, e);
    int dst = load_dst(ei, e);
    int rel = load_rel(et, e);
    if ((unsigned)src >= NN || (unsigned)dst >= NN || (unsigned)rel >= RR) {
        g_stage[e] = ~0ull;
        return;
    }
    int key = dst * RR + rel;
    atomicAdd(&g_cnt[key], 1);
    g_stage[e] = ((ull)(unsigned)key << 32) | (unsigned)src;
}

// ---------------- 2-kernel scan over 400k counts ----------------------------------
__global__ void blocksum_kernel() {
    int b = blockIdx.x, t = threadIdx.x, i = b * 256 + t;
    int v = (i < NR) ? g_cnt[i] : 0;
    __shared__ int sh[8];
    int lane = t & 31, wid = t >> 5;
    #pragma unroll
    for (int o = 16; o > 0; o >>= 1) v += __shfl_xor_sync(0xffffffffu, v, o);
    if (lane == 0) sh[wid] = v;
    __syncthreads();
    if (t == 0) {
        int s = 0;
        #pragma unroll
        for (int j = 0; j < 8; j++) s += sh[j];
        g_bsum[b] = s;
    }
}

__device__ __forceinline__ int block_incl_scan256(int v, int t) {
    __shared__ int ws[8];
    int lane = t & 31, wid = t >> 5;
    int x = v;
    #pragma unroll
    for (int o = 1; o < 32; o <<= 1) {
        int y = __shfl_up_sync(0xffffffffu, x, o);
        if (lane >= o) x += y;
    }
    if (lane == 31) ws[wid] = x;
    __syncthreads();
    if (wid == 0) {
        int s = (lane < 8) ? ws[lane] : 0;
        #pragma unroll
        for (int o = 1; o < 8; o <<= 1) {
            int y = __shfl_up_sync(0xffffffffu, s, o);
            if (lane >= o) s += y;
        }
        if (lane < 8) ws[lane] = s;
    }
    __syncthreads();
    if (wid > 0) x += ws[wid - 1];
    return x;
}

__global__ void offsets2_kernel() {
    int b = blockIdx.x, t = threadIdx.x, i = b * 256 + t;
    int part = 0;
    for (int j = t; j < b; j += 256) part += g_bsum[j];
    __shared__ int red[8];
    __shared__ int sprefix;
    int lane = t & 31, wid = t >> 5;
    #pragma unroll
    for (int o = 16; o > 0; o >>= 1) part += __shfl_xor_sync(0xffffffffu, part, o);
    if (lane == 0) red[wid] = part;
    __syncthreads();
    if (t == 0) {
        int s = 0;
        #pragma unroll
        for (int j = 0; j < 8; j++) s += red[j];
        sprefix = s;
    }
    __syncthreads();

    int v = (i < NR) ? g_cnt[i] : 0;
    int incl = block_incl_scan256(v, t);
    int excl = sprefix + incl - v;
    if (i < NR) { g_ptr[i] = excl; g_cur[i] = excl; }
    if (b == NB2 - 1 && t == 255) g_ptr[NR] = sprefix + incl;
}

// ---------------- scatter (1 edge / thread — proven) ------------------------------
__global__ void scatter_kernel() {
    int e = blockIdx.x * blockDim.x + threadIdx.x;
    if (e >= EE) return;
    ull s = g_stage[e];
    if (s == ~0ull) return;
    int key = (int)(s >> 32);
    unsigned src = (unsigned)s;
    int pos = atomicAdd(&g_cur[key], 1);
    g_packed[pos] = ((unsigned)(key & 7) << 16) | src;
}

// ---------------- tensor-core helpers ------------------------------------------
__device__ __forceinline__ unsigned smem_u32(const void* p) {
    return (unsigned)__cvta_generic_to_shared(p);
}
__device__ __forceinline__ void ldsm4(unsigned& r0, unsigned& r1, unsigned& r2,
                                      unsigned& r3, unsigned addr) {
    asm volatile("ldmatrix.sync.aligned.m8n8.x4.shared.b16 {%0,%1,%2,%3}, [%4];"
                 : "=r"(r0), "=r"(r1), "=r"(r2), "=r"(r3) : "r"(addr));
}
__device__ __forceinline__ void ldsm4t(unsigned& r0, unsigned& r1, unsigned& r2,
                                       unsigned& r3, unsigned addr) {
    asm volatile("ldmatrix.sync.aligned.m8n8.x4.trans.shared.b16 {%0,%1,%2,%3}, [%4];"
                 : "=r"(r0), "=r"(r1), "=r"(r2), "=r"(r3) : "r"(addr));
}
__device__ __forceinline__ void mma16816h(float* d, unsigned a0, unsigned a1,
                                          unsigned a2, unsigned a3,
                                          unsigned b0, unsigned b1) {
    asm volatile(
        "mma.sync.aligned.m16n8k16.row.col.f32.f16.f16.f32 "
        "{%0,%1,%2,%3},{%4,%5,%6,%7},{%8,%9},{%0,%1,%2,%3};"
        : "+f"(d[0]), "+f"(d[1]), "+f"(d[2]), "+f"(d[3])
        : "r"(a0), "r"(a1), "r"(a2), "r"(a3), "r"(b0), "r"(b1));
}

// ---------------- fp16 tensor GEMM: C[128 x 64] per block, double-buffered --------
template <int K>
__global__ void __launch_bounds__(256)
tgemm_kernel(const __half* __restrict__ A, const float* __restrict__ bias,
             int woff, int layer) {
    __shared__ __half sA[2][128 * 40];
    __shared__ __half sB[2][32 * 72];

    int tid = threadIdx.x, warp = tid >> 5, lane = tid & 31;
    int m0 = blockIdx.x * 128, rel = blockIdx.y;

    const __half* W = g_wh + woff + (size_t)rel * K * 64;

    float acc[8][4];
    #pragma unroll
    for (int j = 0; j < 8; j++)
        #pragma unroll
        for (int i = 0; i < 4; i++) acc[j][i] = 0.f;

    const uint4 z4 = make_uint4(0, 0, 0, 0);

    int ar0 = (tid + 0)   >> 2, as0 = (tid + 0)   & 3;
    int ar1 = (tid + 256) >> 2, as1 = (tid + 256) & 3;
    int brow = tid >> 3,  bs = tid & 7;

    {
        uint4 v0 = z4, v1 = z4;
        if (m0 + ar0 < NN) v0 = *(const uint4*)&A[(size_t)(m0 + ar0) * K + as0 * 8];
        if (m0 + ar1 < NN) v1 = *(const uint4*)&A[(size_t)(m0 + ar1) * K + as1 * 8];
        *(uint4*)&sA[0][ar0 * 40 + as0 * 8] = v0;
        *(uint4*)&sA[0][ar1 * 40 + as1 * 8] = v1;
        *(uint4*)&sB[0][brow * 72 + bs * 8] = *(const uint4*)&W[(size_t)brow * 64 + bs * 8];
    }
    __syncthreads();

    #pragma unroll
    for (int it = 0; it < K / 32; it++) {
        int p = it & 1;
        int ktn = (it + 1) * 32;

        uint4 nA0 = z4, nA1 = z4, nB = z4;
        if (ktn < K) {
            if (m0 + ar0 < NN) nA0 = *(const uint4*)&A[(size_t)(m0 + ar0) * K + ktn + as0 * 8];
            if (m0 + ar1 < NN) nA1 = *(const uint4*)&A[(size_t)(m0 + ar1) * K + ktn + as1 * 8];
            nB = *(const uint4*)&W[(size_t)(ktn + brow) * 64 + bs * 8];
        }

        #pragma unroll
        for (int ks = 0; ks < 32; ks += 16) {
            unsigned ah[4];
            unsigned aoff = (warp * 16 + (lane & 15)) * 40 + ks + (lane >> 4) * 8;
            ldsm4(ah[0], ah[1], ah[2], ah[3], smem_u32(&sA[p][aoff]));
            #pragma unroll
            for (int jj = 0; jj < 4; jj++) {
                int g = lane >> 3;
                int br = ks + (lane & 7) + (g & 1) * 8;
                int bc = jj * 16 + (g >> 1) * 8;
                unsigned bh[4];
                ldsm4t(bh[0], bh[1], bh[2], bh[3], smem_u32(&sB[p][br * 72 + bc]));
                mma16816h(acc[2 * jj],     ah[0], ah[1], ah[2], ah[3], bh[0], bh[1]);
                mma16816h(acc[2 * jj + 1], ah[0], ah[1], ah[2], ah[3], bh[2], bh[3]);
            }
        }

        if (ktn < K) {
            *(uint4*)&sA[1 - p][ar0 * 40 + as0 * 8] = nA0;
            *(uint4*)&sA[1 - p][ar1 * 40 + as1 * 8] = nA1;
            *(uint4*)&sB[1 - p][brow * 72 + bs * 8] = nB;
            __syncthreads();
        }
    }

    int row = m0 + warp * 16 + (lane >> 2);
    int cb  = (lane & 3) * 2;
    if (rel < 8) {
        #pragma unroll
        for (int j = 0; j < 8; j++) {
            int col = rel * 64 + j * 8 + cb;
            if (row < NN)
                *(__half2*)&g_H[(size_t)row * 512 + col] =
                    __floats2half2_rn(acc[j][0], acc[j][1]);
            if (row + 8 < NN)
                *(__half2*)&g_H[(size_t)(row + 8) * 512 + col] =
                    __floats2half2_rn(acc[j][2], acc[j][3]);
        }
    } else {
        float* C = (layer == 1) ? g_h1 : g_h2;
        #pragma unroll
        for (int j = 0; j < 8; j++) {
            int col = j * 8 + cb;
            float b0 = bias[col], b1 = bias[col + 1];
            if (row < NN)
                *(float2*)&C[(size_t)row * 64 + col] =
                    make_float2(acc[j][0] + b0, acc[j][1] + b1);
            if (row + 8 < NN)
                *(float2*)&C[(size_t)(row + 8) * 64 + col] =
                    make_float2(acc[j][2] + b0, acc[j][3] + b1);
        }
    }
}

// ---------------- aggregation: warp per node, MLP-8 fp16 gather (R12 exact) ------
__global__ void agg_kernel(int sel) {
    int gw   = (blockIdx.x * blockDim.x + threadIdx.x) >> 5;
    int lane = threadIdx.x & 31;
    if (gw >= NN) return;

    int p0 = 0, p1 = 0;
    if (lane < 8) {
        p0 = g_ptr[gw * RR + lane];
        p1 = g_ptr[gw * RR + lane + 1];
    }
    float inv8 = (lane < 8) ? 1.f / (float)max(p1 - p0, 1) : 0.f;
    int beg = __shfl_sync(0xffffffffu, p0, 0);
    int end = __shfl_sync(0xffffffffu, p1, 7);

    float ax = 0.f, ay = 0.f;
    int e = beg;
    for (; e + 8 <= end; e += 8) {
        unsigned q[8];
        #pragma unroll
        for (int u = 0; u < 8; u++) q[u] = g_packed[e + u];
        __half2 v[8];
        #pragma unroll
        for (int u = 0; u < 8; u++)
            v[u] = *(const __half2*)&g_H[(size_t)(q[u] & 0xffff) * 512 +
                                         (q[u] >> 16) * 64 + lane * 2];
        #pragma unroll
        for (int u = 0; u < 8; u++) {
            float iv = __shfl_sync(0xffffffffu, inv8, q[u] >> 16);
            float2 f = __half22float2(v[u]);
            ax = fmaf(f.x, iv, ax);
            ay = fmaf(f.y, iv, ay);
        }
    }
    for (; e < end; e++) {
        unsigned q = g_packed[e];
        float iv = __shfl_sync(0xffffffffu, inv8, q >> 16);
        __half2 hv = *(const __half2*)&g_H[(size_t)(q & 0xffff) * 512 +
                                           (q >> 16) * 64 + lane * 2];
        float2 f = __half22float2(hv);
        ax = fmaf(f.x, iv, ax);
        ay = fmaf(f.y, iv, ay);
    }

    const float* base = (sel == 1) ? g_h1 : g_h2;
    float2 b = *(const float2*)&base[(size_t)gw * 64 + lane * 2];
    float o0 = b.x + ax, o1 = b.y + ay;
    o0 = o0 > 0.f ? o0 : 0.f;
    o1 = o1 > 0.f ? o1 : 0.f;
    if (sel == 1) {
        ((__half2*)g_ah)[gw * 32 + lane] = __floats2half2_rn(o0, o1);
    } else {
        *(float2*)&g_h2[(size_t)gw * 64 + lane * 2] = make_float2(o0, o1);
    }
}

// ---------------- final: logits = h2 @ Wl + bl, then log_softmax -----------------
__global__ void __launch_bounds__(256)
final_kernel(const float* __restrict__ Wl, const float* __restrict__ bl,
             float* __restrict__ out) {
    __shared__ float sW[64 * 40];
    __shared__ float sb[40];
    __shared__ float srow[8][64];
    int t = threadIdx.x;
    for (int i = t; i < 64 * 40; i += 256) sW[i] = Wl[i];
    if (t < 40) sb[t] = bl[t];
    __syncthreads();

    int warp = t >> 5, lane = t & 31;
    int n = blockIdx.x * 8 + warp;
    if (n < NN) {
        srow[warp][lane]      = g_h2[(size_t)n * 64 + lane];
        srow[warp][lane + 32] = g_h2[(size_t)n * 64 + 32 + lane];
    }
    __syncwarp();

    float v1 = -1e30f, v2 = -1e30f;
    if (n < NN) {
        float d = sb[lane];
        #pragma unroll
        for (int k = 0; k < 64; k++) d += srow[warp][k] * sW[k * 40 + lane];
        v1 = d;
        if (lane < 8) {
            float d2 = sb[lane + 32];
            #pragma unroll
            for (int k = 0; k < 64; k++) d2 += srow[warp][k] * sW[k * 40 + lane + 32];
            v2 = d2;
        }
    }
    float m = fmaxf(v1, v2);
    #pragma unroll
    for (int o = 16; o > 0; o >>= 1) m = fmaxf(m, __shfl_xor_sync(0xffffffffu, m, o));
    float e1 = __expf(v1 - m);
    float e2 = (lane < 8) ? __expf(v2 - m) : 0.f;
    float s = e1 + e2;
    #pragma unroll
    for (int o = 16; o > 0; o >>= 1) s += __shfl_xor_sync(0xffffffffu, s, o);
    float lse = m + __logf(s);
    if (n < NN) {
        out[(size_t)n * 40 + lane] = v1 - lse;
        if (lane < 8) out[(size_t)n * 40 + 32 + lane] = v2 - lse;
    }
}

// ---------------- launch ---------------------------------------------------------
extern "C" void kernel_launch(void* const* d_in, const int* in_sizes, int n_in,
                              void* d_out, int out_size) {
    const float* x     = (const float*)d_in[0];
    const void*  ei    = d_in[1];
    const void*  et    = d_in[2];
    const float* W1    = (const float*)d_in[3];
    const float* root1 = (const float*)d_in[4];
    const float* b1    = (const float*)d_in[5];
    const float* W2    = (const float*)d_in[6];
    const float* root2 = (const float*)d_in[7];
    const float* b2    = (const float*)d_in[8];
    const float* Wl    = (const float*)d_in[9];
    const float* bl    = (const float*)d_in[10];
    float*       out   = (float*)d_out;

    __half *xh, *ah;
    cudaGetSymbolAddress((void**)&xh, g_xh);
    cudaGetSymbolAddress((void**)&ah, g_ah);

    // one-time resources (identical captured work every call)
    static cudaStream_t s1 = nullptr;
    static cudaEvent_t evFork = nullptr, evJoin = nullptr;
    if (s1 == nullptr) {
        cudaStreamCreateWithFlags(&s1, cudaStreamNonBlocking);
        cudaEventCreateWithFlags(&evFork, cudaEventDisableTiming);
        cudaEventCreateWithFlags(&evJoin, cudaEventDisableTiming);
    }

    dim3 g9((NN + 127) / 128, 9);

    // fork: side stream runs the dense chain (conversions + tgemm layer 1)
    cudaEventRecord(evFork, 0);
    cudaStreamWaitEvent(s1, evFork, 0);

    prep_dense_kernel<<<(X_F2 + 255) / 256, 256, 0, s1>>>(x, W1, root1, W2, root2);
    tgemm_kernel<128><<<g9, 256, 0, s1>>>(xh, b1, 0, 1);
    cudaEventRecord(evJoin, s1);

    // main (legacy) stream runs the edge chain
    prep_edge_kernel<<<NB2, 256>>>((const unsigned*)ei, (const unsigned*)et);
    hist_stage_kernel<<<(EE + 255) / 256, 256>>>(ei, et);
    blocksum_kernel<<<NB2, 256>>>();
    offsets2_kernel<<<NB2, 256>>>();
    scatter_kernel<<<(EE + 255) / 256, 256>>>();

    // join: agg1 needs both branches
    cudaStreamWaitEvent(0, evJoin, 0);

    agg_kernel<<<(NN * 32 + 255) / 256, 256>>>(1);     // -> g_ah (fp16)
    tgemm_kernel<64><<<g9, 256>>>(ah, b2, W2OFF, 2);
    agg_kernel<<<(NN * 32 + 255) / 256, 256>>>(2);     // -> g_h2 (fp32)
    final_kernel<<<(NN + 7) / 8, 256>>>(Wl, bl, out);
}